// round 7
// baseline (speedup 1.0000x reference)
#include <cuda_runtime.h>
#include <cuda_bf16.h>

#define FRAME_L   1024
#define HOP       256
#define MAXNF     33024   // >= 32765, padded

// Scratch (no cudaMalloc allowed): per-frame params + hann table.
// g_params[f] = {scale (<0 means invalid/unvoiced), new_len as float}
__device__ float2 g_params[MAXNF];
__device__ __align__(16) float g_hann[FRAME_L];

__global__ void psola_init_kernel(const float* __restrict__ src_f0,
                                  const float* __restrict__ tgt_f0,
                                  const int* __restrict__ voiced,
                                  int nf)
{
    int i = blockIdx.x * blockDim.x + threadIdx.x;
    if (i < FRAME_L) {
        g_hann[i] = 0.5f - 0.5f * cosf(6.28318530717958647692f * (float)i / (float)FRAME_L);
    }
    if (i < nf) {
        float s = src_f0[i];
        float t = tgt_f0[i];
        bool valid = (voiced[i] != 0) && (s >= 1.0f) && (t >= 1.0f);
        float denom = (t >= 1.0f) ? t : 1.0f;
        float ratio = fminf(fmaxf(s / denom, 0.25f), 4.0f);
        // jnp.round is round-half-to-even -> rintf (device default RN mode)
        float nl = fmaxf(1.0f, rintf((float)FRAME_L * ratio));
        float scale = (float)FRAME_L / nl;
        float2 p;
        p.x = valid ? scale : -1.0f;
        p.y = nl;
        g_params[i] = p;
    }
}

// Each thread produces 4 consecutive output samples (aligned float4).
// All threads of a warp share the same fmax (warp covers 128 samples,
// hop=256), so frame params / branches are warp-uniform.
//
// Interior samples: the 4 quadrature hann phases sum to exactly 2.0
//   -> normalize by *0.5f (no fdiv).
// Gather: upper clip on x removed (dead for counted lanes, address-safe via
// IMNMX); b loaded at [addr+4]; x_i = fma(i, scale, x_base).
__global__ void __launch_bounds__(256)
psola_main_kernel(const float* __restrict__ wav,
                  float* __restrict__ out,
                  int T, int nf)
{
    int t4 = (blockIdx.x * blockDim.x + threadIdx.x) << 2;
    if (t4 >= T) return;

    int fmax = t4 >> 8;          // floor(t/HOP); uniform across warp
    int jb   = t4 & 255;         // t mod HOP (multiple of 4)

    bool interior = (fmax >= 3) & (fmax <= nf - 1);

    // Per-frame params (warp-uniform broadcast loads).
    float scale_k[4], nlen_k[4];
    bool  vo[4], inr[4];
    bool  any_unvoiced = false;
    #pragma unroll
    for (int k = 0; k < 4; k++) {
        int f = fmax - k;
        inr[k] = interior | ((f >= 0) & (f < nf));
        float2 p = inr[k] ? g_params[f] : make_float2(-1.0f, 1.0f);
        vo[k] = (p.x >= 0.0f);
        scale_k[k] = p.x;
        nlen_k[k]  = p.y;
        any_unvoiced |= (inr[k] & !vo[k]);
    }

    // Passthrough samples needed only if some covering frame is unvoiced.
    float wt[4] = {0.f, 0.f, 0.f, 0.f};
    if (any_unvoiced) {
        float4 wt4 = *reinterpret_cast<const float4*>(wav + t4);
        wt[0] = wt4.x; wt[1] = wt4.y; wt[2] = wt4.z; wt[3] = wt4.w;
    }

    float acc[4] = {0.f, 0.f, 0.f, 0.f};
    float ws[4]  = {0.f, 0.f, 0.f, 0.f};   // edge path only

    #pragma unroll
    for (int k = 0; k < 4; k++) {
        if (!inr[k]) continue;

        int f = fmax - k;
        const float* __restrict__ fr = wav + (f << 8);   // frame start
        int   j0    = jb + (k << 8);                     // in [0,1024), 4-aligned
        float scale = scale_k[k];

        float jf0   = (float)j0;                         // exact
        float rem   = nlen_k[k] - jf0;                   // exact (ints < 2^24)
        float xbase = fmaf(jf0 + 0.5f, scale, -0.5f);    // x at i=0

        // 4 contiguous hann weights in one 128-bit load
        float4 h4 = *reinterpret_cast<const float4*>(g_hann + j0);
        float hk[4] = {h4.x, h4.y, h4.z, h4.w};

        #pragma unroll
        for (int i = 0; i < 4; i++) {
            float hw = hk[i];
            if (!interior) ws[i] += hw;

            float c;
            if (!vo[k]) {
                c = wt[i];          // passthrough: frames[f][j] == wav[t]
            } else {
                float x  = fmaxf(fmaf((float)i, scale, xbase), 0.0f);
                int   x0 = min(__float2int_rd(x), FRAME_L - 2);
                float w  = x - (float)x0;
                float a  = __ldg(fr + x0);
                float b  = __ldg(fr + x0 + 1);   // immediate +4B offset
                float v  = fmaf(b - a, w, a);
                c = ((float)i < rem) ? v : 0.0f;
            }
            acc[i] = fmaf(c, hw, acc[i]);
        }
    }

    float4 r;
    if (interior) {
        r.x = acc[0] * 0.5f;
        r.y = acc[1] * 0.5f;
        r.z = acc[2] * 0.5f;
        r.w = acc[3] * 0.5f;
    } else {
        r.x = (ws[0] > 1e-8f) ? acc[0] / ws[0] : acc[0];
        r.y = (ws[1] > 1e-8f) ? acc[1] / ws[1] : acc[1];
        r.z = (ws[2] > 1e-8f) ? acc[2] / ws[2] : acc[2];
        r.w = (ws[3] > 1e-8f) ? acc[3] / ws[3] : acc[3];
    }
    *reinterpret_cast<float4*>(out + t4) = r;
}

extern "C" void kernel_launch(void* const* d_in, const int* in_sizes, int n_in,
                              void* d_out, int out_size)
{
    const float* wav    = (const float*)d_in[0];
    const float* src_f0 = (const float*)d_in[1];
    const float* tgt_f0 = (const float*)d_in[2];
    const int*   voiced = (const int*)d_in[3];
    float* out = (float*)d_out;

    int T  = in_sizes[0];
    int nf_cap = (T - FRAME_L) / HOP + 1;
    int nf = in_sizes[1] < nf_cap ? in_sizes[1] : nf_cap;
    if (nf > MAXNF) nf = MAXNF;

    {
        int work = nf > FRAME_L ? nf : FRAME_L;
        int threads = 256;
        int blocks = (work + threads - 1) / threads;
        psola_init_kernel<<<blocks, threads>>>(src_f0, tgt_f0, voiced, nf);
    }
    {
        int threads = 256;
        int n4 = (T + 3) / 4;
        int blocks = (n4 + threads - 1) / threads;
        psola_main_kernel<<<blocks, threads>>>(wav, out, T, nf);
    }
}

// round 8
// speedup vs baseline: 1.0495x; 1.0495x over previous
#include <cuda_runtime.h>
#include <cuda_bf16.h>

#define FRAME_L   1024
#define HOP       256
#define MAXNF     33024   // >= 32765, padded

// Scratch (no cudaMalloc allowed): per-frame params + hann table.
// g_params[f] = {scale, new_len}. Invalid/unvoiced frames get {1.0, 1024}:
// with scale=1 the resample path reproduces the passthrough EXACTLY in fp32
// (x = (j+0.5)*1 - 0.5 = j, w = 0), so the main kernel needs no branch.
__device__ float2 g_params[MAXNF];
__device__ __align__(16) float g_hann[FRAME_L];

__global__ void psola_init_kernel(const float* __restrict__ src_f0,
                                  const float* __restrict__ tgt_f0,
                                  const int* __restrict__ voiced,
                                  int nf)
{
    int i = blockIdx.x * blockDim.x + threadIdx.x;
    if (i < FRAME_L) {
        g_hann[i] = 0.5f - 0.5f * cosf(6.28318530717958647692f * (float)i / (float)FRAME_L);
    }
    if (i < nf) {
        float s = src_f0[i];
        float t = tgt_f0[i];
        bool valid = (voiced[i] != 0) && (s >= 1.0f) && (t >= 1.0f);
        float denom = (t >= 1.0f) ? t : 1.0f;
        float ratio = fminf(fmaxf(s / denom, 0.25f), 4.0f);
        // jnp.round is round-half-to-even -> rintf (device default RN mode)
        float nl = fmaxf(1.0f, rintf((float)FRAME_L * ratio));
        float2 p;
        p.x = valid ? ((float)FRAME_L / nl) : 1.0f;
        p.y = valid ? nl : (float)FRAME_L;
        g_params[i] = p;
    }
}

// Each thread produces 4 consecutive output samples (aligned float4).
// All threads of a warp share the same fmax, so param loads broadcast and
// the interior/edge branch is warp-uniform.
// Interior samples: the 4 quadrature hann phases sum to exactly 2.0
//   -> normalize by *0.5f (no fdiv).
__global__ void __launch_bounds__(256)
psola_main_kernel(const float* __restrict__ wav,
                  float* __restrict__ out,
                  int T, int nf)
{
    int t4 = (blockIdx.x * blockDim.x + threadIdx.x) << 2;
    if (t4 >= T) return;

    int fmax = t4 >> 8;          // floor(t/HOP); uniform across warp
    int jb   = t4 & 255;         // t mod HOP (multiple of 4)

    bool interior = (fmax >= 3) & (fmax <= nf - 1);

    float acc[4] = {0.f, 0.f, 0.f, 0.f};
    float ws[4]  = {0.f, 0.f, 0.f, 0.f};   // edge path only

    #pragma unroll
    for (int k = 0; k < 4; k++) {
        int f = fmax - k;
        if (!interior) {
            if (f < 0 || f >= nf) continue;
        }

        float2 p = g_params[f];
        const float* __restrict__ fr = wav + (f << 8);   // frame start
        int   j0    = jb + (k << 8);                     // in [0,1024), 4-aligned
        float scale = p.x;

        float jf0   = (float)j0;                         // exact
        float rem   = p.y - jf0;                         // exact (ints < 2^24)
        float xbase = fmaf(jf0 + 0.5f, scale, -0.5f);    // x at i=0

        // 4 contiguous hann weights in one 128-bit load
        float4 h4 = *reinterpret_cast<const float4*>(g_hann + j0);
        float hk[4] = {h4.x, h4.y, h4.z, h4.w};

        #pragma unroll
        for (int i = 0; i < 4; i++) {
            float hw = hk[i];
            if (!interior) ws[i] += hw;

            float x  = fmaxf(fmaf((float)i, scale, xbase), 0.0f);
            int   x0 = min(__float2int_rd(x), FRAME_L - 2);
            float w  = x - (float)x0;
            float a  = __ldg(fr + x0);
            float b  = __ldg(fr + x0 + 1);   // immediate +4B offset
            float v  = fmaf(b - a, w, a);
            float c  = ((float)i < rem) ? v : 0.0f;
            acc[i] = fmaf(c, hw, acc[i]);
        }
    }

    float4 r;
    if (interior) {
        r.x = acc[0] * 0.5f;
        r.y = acc[1] * 0.5f;
        r.z = acc[2] * 0.5f;
        r.w = acc[3] * 0.5f;
    } else {
        r.x = (ws[0] > 1e-8f) ? acc[0] / ws[0] : acc[0];
        r.y = (ws[1] > 1e-8f) ? acc[1] / ws[1] : acc[1];
        r.z = (ws[2] > 1e-8f) ? acc[2] / ws[2] : acc[2];
        r.w = (ws[3] > 1e-8f) ? acc[3] / ws[3] : acc[3];
    }
    *reinterpret_cast<float4*>(out + t4) = r;
}

extern "C" void kernel_launch(void* const* d_in, const int* in_sizes, int n_in,
                              void* d_out, int out_size)
{
    const float* wav    = (const float*)d_in[0];
    const float* src_f0 = (const float*)d_in[1];
    const float* tgt_f0 = (const float*)d_in[2];
    const int*   voiced = (const int*)d_in[3];
    float* out = (float*)d_out;

    int T  = in_sizes[0];
    int nf_cap = (T - FRAME_L) / HOP + 1;
    int nf = in_sizes[1] < nf_cap ? in_sizes[1] : nf_cap;
    if (nf > MAXNF) nf = MAXNF;

    {
        int work = nf > FRAME_L ? nf : FRAME_L;
        int threads = 256;
        int blocks = (work + threads - 1) / threads;
        psola_init_kernel<<<blocks, threads>>>(src_f0, tgt_f0, voiced, nf);
    }
    {
        int threads = 256;
        int n4 = (T + 3) / 4;
        int blocks = (n4 + threads - 1) / threads;
        psola_main_kernel<<<blocks, threads>>>(wav, out, T, nf);
    }
}

// round 9
// speedup vs baseline: 1.1146x; 1.0621x over previous
#include <cuda_runtime.h>
#include <cuda_bf16.h>

#define FRAME_L   1024
#define HOP       256

// ---------------------------------------------------------------------------
// Compile-time half-Hann table: g_hh.v[i] = 0.5 * (0.5 - 0.5*cos(2*pi*i/1024))
// Storing hann/2 lets the interior path skip its final *0.5 (exact: scaling by
// 2^-1 commutes with fp rounding), and the edge path's acc/ws ratio is
// bit-identical under joint halving.
// ---------------------------------------------------------------------------
struct alignas(16) HannTab { float v[FRAME_L]; };

constexpr double kPI = 3.141592653589793238462643383279502884;

constexpr double ccos_core(double x) {   // |x| <= pi/2, Taylor, err < 1e-16
    double x2 = x * x, s = 1.0, term = 1.0;
    for (int k = 1; k <= 10; k++) { term *= -x2 / (double)((2*k-1)*(2*k)); s += term; }
    return s;
}
constexpr double ccos(double x) {        // x in [0, 2*pi)
    if (x > kPI) x = 2.0 * kPI - x;
    if (x > 0.5 * kPI) return -ccos_core(kPI - x);
    return ccos_core(x);
}
constexpr HannTab make_half_hann() {
    HannTab t{};
    for (int i = 0; i < FRAME_L; i++) {
        double th = (2.0 * kPI * (double)i) / (double)FRAME_L;
        t.v[i] = (float)(0.5 * (0.5 - 0.5 * ccos(th)));
    }
    return t;
}
__device__ constexpr HannTab g_hh = make_half_hann();

// ---------------------------------------------------------------------------
// Single kernel. Each thread produces 4 consecutive output samples (float4).
// A block covers 1024 samples -> exactly 7 covering frames; threads 0..7
// compute their params (IEEE divides, must match jnp fp32 exactly so rintf
// doesn't flip) into smem once per block.
//
// Invalid/unvoiced frames get {scale=1, nlen=1024}: with scale=1 the resample
// path reproduces passthrough EXACTLY in fp32, so the datapath is branch-free.
// Interior samples: the 4 quadrature hann phases sum to exactly 2.0 -> with
// the pre-halved table, no normalization at all.
// ---------------------------------------------------------------------------
__global__ void __launch_bounds__(256)
psola_kernel(const float* __restrict__ wav,
             const float* __restrict__ src_f0,
             const float* __restrict__ tgt_f0,
             const int*   __restrict__ voiced,
             float* __restrict__ out,
             int T, int nf)
{
    __shared__ float2 s_par[8];

    int fbase = ((int)blockIdx.x << 2) - 3;     // first frame this block can touch
    if (threadIdx.x < 8) {
        int f = fbase + (int)threadIdx.x;
        float2 p = make_float2(1.0f, (float)FRAME_L);
        if (f >= 0 && f < nf) {
            float s = src_f0[f];
            float t = tgt_f0[f];
            if ((voiced[f] != 0) && (s >= 1.0f) && (t >= 1.0f)) {
                // t >= 1 here, so denom == t (matches reference's where())
                float ratio = fminf(fmaxf(s / t, 0.25f), 4.0f);
                float nl = fmaxf(1.0f, rintf((float)FRAME_L * ratio));
                p = make_float2((float)FRAME_L / nl, nl);
            }
        }
        s_par[threadIdx.x] = p;
    }
    __syncthreads();

    int t4 = ((int)(blockIdx.x * blockDim.x + threadIdx.x)) << 2;
    if (t4 >= T) return;

    int fmax  = t4 >> 8;          // floor(t/HOP); uniform across warp
    int jb    = t4 & 255;         // t mod HOP (multiple of 4)
    int sbase = fmax - fbase;     // smem slot for k=0 (in [3,6])

    bool interior = (fmax >= 3) & (fmax <= nf - 1);

    float acc[4] = {0.f, 0.f, 0.f, 0.f};
    float ws[4]  = {0.f, 0.f, 0.f, 0.f};   // edge path only (half-hann sums)

    #pragma unroll
    for (int k = 0; k < 4; k++) {
        int f = fmax - k;
        if (!interior) {
            if (f < 0 || f >= nf) continue;
        }

        float2 p = s_par[sbase - k];
        const float* __restrict__ fr = wav + (f << 8);   // frame start
        int   j0    = jb + (k << 8);                     // in [0,1024), 4-aligned
        float scale = p.x;

        float jf0   = (float)j0;                         // exact
        float rem   = p.y - jf0;                         // exact (ints < 2^24)
        float xbase = fmaf(jf0 + 0.5f, scale, -0.5f);    // x at i=0

        // 4 contiguous half-hann weights in one 128-bit load
        float4 h4 = *reinterpret_cast<const float4*>(g_hh.v + j0);
        float hk[4] = {h4.x, h4.y, h4.z, h4.w};

        #pragma unroll
        for (int i = 0; i < 4; i++) {
            float hw = hk[i];
            if (!interior) ws[i] += hw;

            float x  = fmaxf(fmaf((float)i, scale, xbase), 0.0f);
            int   x0 = min(__float2int_rd(x), FRAME_L - 2);
            float w  = x - (float)x0;
            float a  = __ldg(fr + x0);
            float b  = __ldg(fr + x0 + 1);   // immediate +4B offset
            float v  = fmaf(b - a, w, a);
            float c  = ((float)i < rem) ? v : 0.0f;
            acc[i] = fmaf(c, hw, acc[i]);
        }
    }

    float4 r;
    if (interior) {
        // Quadrature hann phases sum to exactly 2; table is pre-halved.
        r.x = acc[0];
        r.y = acc[1];
        r.z = acc[2];
        r.w = acc[3];
    } else {
        // acc and ws are both exactly half their reference values -> identical
        // ratio. Threshold safe: partial hann sums are 0 or >= 9.4e-6.
        r.x = (ws[0] > 1e-8f) ? acc[0] / ws[0] : acc[0];
        r.y = (ws[1] > 1e-8f) ? acc[1] / ws[1] : acc[1];
        r.z = (ws[2] > 1e-8f) ? acc[2] / ws[2] : acc[2];
        r.w = (ws[3] > 1e-8f) ? acc[3] / ws[3] : acc[3];
    }
    *reinterpret_cast<float4*>(out + t4) = r;
}

extern "C" void kernel_launch(void* const* d_in, const int* in_sizes, int n_in,
                              void* d_out, int out_size)
{
    const float* wav    = (const float*)d_in[0];
    const float* src_f0 = (const float*)d_in[1];
    const float* tgt_f0 = (const float*)d_in[2];
    const int*   voiced = (const int*)d_in[3];
    float* out = (float*)d_out;

    int T  = in_sizes[0];
    int nf_cap = (T - FRAME_L) / HOP + 1;
    int nf = in_sizes[1] < nf_cap ? in_sizes[1] : nf_cap;

    int threads = 256;
    int n4 = (T + 3) / 4;
    int blocks = (n4 + threads - 1) / threads;
    psola_kernel<<<blocks, threads>>>(wav, src_f0, tgt_f0, voiced, out, T, nf);
}